// round 7
// baseline (speedup 1.0000x reference)
#include <cuda_runtime.h>

// Occupancy connectivity loss over a 385^3 fp32 grid, C order:
//   f = x*385^2 + y*385 + z
// Block = 8 warps = 8 consecutive y-rows of a 128-wide z segment (+1 halo
// column), marching over an x chunk. Global loads are 4 coalesced LDG.32
// per warp-row (+ lane31 halo) into prefetch regs; published to smem; each
// lane then reads back float4 at [4*lane] (smem is aligned even though the
// global rows are not):
//   x-diff: previous plane's readback registers
//   z-diff: 3 in-register + 1 scalar LDS at [4*lane+4]
//   y-diff: LDS.128 from neighbor warp's smem row
// Rows loaded 8, owned 7. Double-buffered smem; peeled branch-free body.

#define ROW    385u
#define PLANE  148225u
#define WPB    8u
#define OWN    7u
#define NYG    55u
#define XC     7u
#define NZSEG  3u
#define NBLOCKS (NZSEG * NYG * XC)   // 1155

__device__ double   g_part[NBLOCKS];
__device__ unsigned g_count = 0;

__global__ void __launch_bounds__(256, 8)
occ_main(const float* __restrict__ occ, float* __restrict__ out) {
    const unsigned wid  = threadIdx.x >> 5;
    const unsigned lane = threadIdx.x & 31u;
    const bool     l31  = (lane == 31u);

    const unsigned zseg = blockIdx.x % NZSEG;
    const unsigned rest = blockIdx.x / NZSEG;
    const unsigned xc   = rest % XC;
    const unsigned g    = rest / XC;

    const unsigned zb = zseg * 128u;
    const unsigned yb = g * OWN;
    const unsigned y  = yb + wid;
    const bool rowload = (y <= 384u);
    const bool rowown  = (wid < OWN) && rowload;
    const bool ypair   = rowown && (y < 384u);
    const bool hseg31  = (zseg == NZSEG - 1u) && l31;  // z=384 column diffs

    const unsigned as = (384u * xc) / XC;
    const unsigned ae = (384u * (xc + 1u)) / XC;
    const bool lastc  = (ae == 384u);
    const int  mid    = (int)(ae - as) - 1;

    __shared__ float sm[2][WPB][132];

    const float* pn = occ + (size_t)y * ROW + zb + lane + (size_t)as * PLANE;

    float s0 = 0.0f, s1 = 0.0f;
    float n0=0.f,n1=0.f,n2=0.f,n3=0.f,hn=0.f;   // prefetch regs
    float4 c  = make_float4(0.f,0.f,0.f,0.f);   // current readback
    float4 cp = c;                              // previous readback
    float  ch = 0.f, chp = 0.f;

    #define LDROW(P) do {                                       \
        n0=__ldg(P); n1=__ldg((P)+32);                          \
        n2=__ldg((P)+64); n3=__ldg((P)+96);                     \
        if (l31) hn=__ldg((P)+97); } while(0)

    #define PUBN(B) do { float* r_ = sm[B][wid];                \
        r_[lane]=n0; r_[lane+32u]=n1;                           \
        r_[lane+64u]=n2; r_[lane+96u]=n3;                       \
        if (l31) r_[128]=hn; } while(0)

    #define READBK(B) do {                                      \
        c  = *reinterpret_cast<const float4*>(&sm[B][wid][4u*lane]); \
        ch = sm[B][wid][4u*lane + 4u]; } while(0)

    #define ZY(B) do {                                                      \
        s0 += fabsf(c.y-c.x) + fabsf(c.z-c.y);                              \
        s1 += fabsf(c.w-c.z) + fabsf(ch -c.w);                              \
        if (ypair) {                                                        \
            float4 d_ = *reinterpret_cast<const float4*>(&sm[B][wid+1u][4u*lane]); \
            s0 += fabsf(d_.x-c.x) + fabsf(d_.y-c.y);                        \
            s1 += fabsf(d_.z-c.z) + fabsf(d_.w-c.w);                        \
            if (hseg31) s0 += fabsf(sm[B][wid+1u][128] - ch);               \
        } } while(0)

    #define XD() do {                                                       \
        s0 += fabsf(c.x-cp.x) + fabsf(c.y-cp.y);                            \
        s1 += fabsf(c.z-cp.z) + fabsf(c.w-cp.w);                            \
        if (hseg31) s0 += fabsf(ch-chp); } while(0)

    // ---- first plane (x = as): z/y diffs only ----
    if (rowload) { LDROW(pn); PUBN(0); pn += PLANE; LDROW(pn); }
    __syncthreads();
    if (rowown) { READBK(0); ZY(0); cp = c; chp = ch; }

    // ---- steady planes (x = as+1 .. ae-1): branch-free body ----
    unsigned buf = 1u;
    #pragma unroll 2
    for (int i = 0; i < mid; ++i) {
        if (rowload) { PUBN(buf); pn += PLANE; LDROW(pn); }
        __syncthreads();
        if (rowown) { READBK(buf); XD(); ZY(buf); cp = c; chp = ch; }
        buf ^= 1u;
    }

    // ---- last plane (x = ae): x-diffs always, z/y only in last chunk ----
    if (rowload) PUBN(buf);
    __syncthreads();
    if (rowown) { READBK(buf); XD(); if (lastc) ZY(buf); }

    // ---- block reduction ----
    float s = s0 + s1;
    #pragma unroll
    for (int o = 16; o > 0; o >>= 1)
        s += __shfl_down_sync(0xffffffffu, s, o);

    __shared__ float    ws[WPB];
    __shared__ unsigned islast_s;
    if (lane == 0u) ws[wid] = s;
    __syncthreads();
    if (threadIdx.x == 0u) {
        float t = 0.f;
        #pragma unroll
        for (unsigned i = 0; i < WPB; ++i) t += ws[i];
        g_part[blockIdx.x] = (double)t;
        __threadfence();
        unsigned old = atomicAdd(&g_count, 1u);
        islast_s = (old == NBLOCKS - 1u) ? 1u : 0u;
    }
    __syncthreads();

    // ---- last block folds partials (single launch total) ----
    if (islast_s) {
        double d = 0.0;
        for (unsigned i = threadIdx.x; i < NBLOCKS; i += 256u)
            d += g_part[i];
        __shared__ double dsm[256];
        dsm[threadIdx.x] = d;
        __syncthreads();
        #pragma unroll
        for (int st = 128; st > 0; st >>= 1) {
            if ((int)threadIdx.x < st) dsm[threadIdx.x] += dsm[threadIdx.x + st];
            __syncthreads();
        }
        if (threadIdx.x == 0u) {
            out[0] = (float)dsm[0];
            g_count = 0u;   // reset for next graph replay
        }
    }
}

extern "C" void kernel_launch(void* const* d_in, const int* in_sizes, int n_in,
                              void* d_out, int out_size) {
    const float* occ = (const float*)d_in[0];
    float* out = (float*)d_out;
    occ_main<<<NBLOCKS, 256>>>(occ, out);
}

// round 8
// speedup vs baseline: 1.1065x; 1.1065x over previous
#include <cuda_runtime.h>

// Occupancy connectivity loss over a 385^3 fp32 grid, C order:
//   f = x*385^2 + y*385 + z
// Block = 8 warps = 8 consecutive y-rows of a 128-wide z segment (+1 halo
// column), marching over an x chunk. Per plane each warp loads its row ONCE
// (4 coalesced LDG.32 + lane31 halo). Center stays in registers.
//   x-diff: |n - v| between current regs and the prefetched next plane
//           (no prev-plane register set needed)
//   z-diff: own smem row at [idx+1] (conflict-free scalar LDS)
//   y-diff: neighbor warp's smem row
// Rows loaded 8, owned 7. Double-buffered smem. 8 blocks/SM.

#define ROW    385u
#define PLANE  148225u
#define WPB    8u
#define OWN    7u
#define NYG    55u
#define XC     7u
#define NZSEG  3u
#define NBLOCKS (NZSEG * NYG * XC)   // 1155

__device__ double   g_part[NBLOCKS];
__device__ unsigned g_count = 0;

__global__ void __launch_bounds__(256, 8)
occ_main(const float* __restrict__ occ, float* __restrict__ out) {
    const unsigned wid  = threadIdx.x >> 5;
    const unsigned lane = threadIdx.x & 31u;
    const bool     l31  = (lane == 31u);

    const unsigned zseg = blockIdx.x % NZSEG;
    const unsigned rest = blockIdx.x / NZSEG;
    const unsigned xc   = rest % XC;
    const unsigned g    = rest / XC;

    const unsigned zb = zseg * 128u;
    const unsigned y  = g * OWN + wid;
    const bool rowload = (y <= 384u);
    const bool rowown  = (wid < OWN);           // implies y <= 384
    const bool ypair   = rowown && (y < 384u);
    const bool hseg31  = (zseg == NZSEG - 1u) && l31;  // z=384 column diffs

    const unsigned as = (384u * xc) / XC;
    const unsigned ae = (384u * (xc + 1u)) / XC;
    const bool lastc  = (ae == 384u);
    const int  mid    = (int)(ae - as);         // planes with a successor

    __shared__ float sm[2][WPB][132];

    const float* p = occ + (size_t)y * ROW + zb + lane + (size_t)as * PLANE;

    float s0 = 0.f, s1 = 0.f;
    float v0=0.f,v1=0.f,v2=0.f,v3=0.f,hc=0.f;
    if (rowload) {
        v0=__ldg(p); v1=__ldg(p+32); v2=__ldg(p+64); v3=__ldg(p+96);
        if (l31) hc=__ldg(p+97);
    }

    unsigned buf = 0u;
    #pragma unroll 2
    for (int i = 0; i < mid; ++i) {
        float n0=0.f,n1=0.f,n2=0.f,n3=0.f,hn=0.f;
        if (rowload) {
            float* r = sm[buf][wid];
            r[lane]=v0; r[lane+32u]=v1; r[lane+64u]=v2; r[lane+96u]=v3;
            if (l31) r[128]=hc;
            p += PLANE;
            n0=__ldg(p); n1=__ldg(p+32); n2=__ldg(p+64); n3=__ldg(p+96);
            if (l31) hn=__ldg(p+97);
        }
        __syncthreads();
        if (rowown) {
            const float* r = sm[buf][wid];
            // z-diffs (neighbor z+1 from own published row, incl. halo col)
            s0 += fabsf(r[lane+1u]  - v0) + fabsf(r[lane+33u] - v1);
            s1 += fabsf(r[lane+65u] - v2) + fabsf(r[lane+97u] - v3);
            if (ypair) {
                const float* q = sm[buf][wid+1u];
                s0 += fabsf(q[lane]      - v0) + fabsf(q[lane+32u] - v1);
                s1 += fabsf(q[lane+64u]  - v2) + fabsf(q[lane+96u] - v3);
                if (hseg31) s0 += fabsf(q[128] - hc);
            }
            // x-diffs for pair (x, x+1) directly vs prefetched regs
            s0 += fabsf(n0 - v0) + fabsf(n1 - v1);
            s1 += fabsf(n2 - v2) + fabsf(n3 - v3);
            if (hseg31) s0 += fabsf(hn - hc);
        }
        v0=n0; v1=n1; v2=n2; v3=n3; hc=hn;
        buf ^= 1u;
    }

    // ---- final plane (x = 384) exists only for the last chunk ----
    if (lastc) {
        if (rowload) {
            float* r = sm[buf][wid];
            r[lane]=v0; r[lane+32u]=v1; r[lane+64u]=v2; r[lane+96u]=v3;
            if (l31) r[128]=hc;
        }
        __syncthreads();
        if (rowown) {
            const float* r = sm[buf][wid];
            s0 += fabsf(r[lane+1u]  - v0) + fabsf(r[lane+33u] - v1);
            s1 += fabsf(r[lane+65u] - v2) + fabsf(r[lane+97u] - v3);
            if (ypair) {
                const float* q = sm[buf][wid+1u];
                s0 += fabsf(q[lane]      - v0) + fabsf(q[lane+32u] - v1);
                s1 += fabsf(q[lane+64u]  - v2) + fabsf(q[lane+96u] - v3);
                if (hseg31) s0 += fabsf(q[128] - hc);
            }
        }
    }

    // ---- block reduction ----
    float s = s0 + s1;
    #pragma unroll
    for (int o = 16; o > 0; o >>= 1)
        s += __shfl_down_sync(0xffffffffu, s, o);

    __shared__ float    ws[WPB];
    __shared__ unsigned islast_s;
    if (lane == 0u) ws[wid] = s;
    __syncthreads();
    if (threadIdx.x == 0u) {
        float t = 0.f;
        #pragma unroll
        for (unsigned i = 0; i < WPB; ++i) t += ws[i];
        g_part[blockIdx.x] = (double)t;
        __threadfence();
        unsigned old = atomicAdd(&g_count, 1u);
        islast_s = (old == NBLOCKS - 1u) ? 1u : 0u;
    }
    __syncthreads();

    // ---- last block folds partials (single launch total) ----
    if (islast_s) {
        double d = 0.0;
        for (unsigned i = threadIdx.x; i < NBLOCKS; i += 256u)
            d += g_part[i];
        __shared__ double dsm[256];
        dsm[threadIdx.x] = d;
        __syncthreads();
        #pragma unroll
        for (int st = 128; st > 0; st >>= 1) {
            if ((int)threadIdx.x < st) dsm[threadIdx.x] += dsm[threadIdx.x + st];
            __syncthreads();
        }
        if (threadIdx.x == 0u) {
            out[0] = (float)dsm[0];
            g_count = 0u;   // reset for next graph replay
        }
    }
}

extern "C" void kernel_launch(void* const* d_in, const int* in_sizes, int n_in,
                              void* d_out, int out_size) {
    const float* occ = (const float*)d_in[0];
    float* out = (float*)d_out;
    occ_main<<<NBLOCKS, 256>>>(occ, out);
}